// round 2
// baseline (speedup 1.0000x reference)
#include <cuda_runtime.h>
#include <math.h>

#define BATCH 2
#define CDIM 256
#define NTOK 4096
#define NHEAD 8
#define DK 32
#define DHALF 128

// Scratch (allowed: __device__ globals)
__device__ float g_tok[BATCH * NTOK * CDIM];
__device__ float g_q[BATCH * NHEAD * NTOK * DK];
__device__ float g_k[BATCH * NHEAD * NTOK * DK];
__device__ float g_v[BATCH * NHEAD * NTOK * DK];
__device__ float g_att[BATCH * NTOK * CDIM];

// 2D positional encoding, faithful to reference:
// d = C/2 = 128; div_term[k] = exp(-(2k) * ln(10000)/d), k = 0..63
// pe[2k]       = sin(w * div[k]);  pe[2k+1]     = cos(w * div[k])
// pe[d+2k]     = sin(h * div[k]);  pe[d+2k+1]   = cos(h * div[k])
__device__ __forceinline__ float pe_val(int c, int n) {
    int hh = n >> 6;
    int ww = n & 63;
    float pos;
    int cc;
    if (c < DHALF) { pos = (float)ww; cc = c; }
    else           { pos = (float)hh; cc = c - DHALF; }
    int j = cc >> 1;
    // ln(10000)/128 = 0.0719557841560...
    float dv = __expf(-(float)(2 * j) * 0.071955784156063940f);
    float a = pos * dv;
    return (cc & 1) ? cosf(a) : sinf(a);
}

// tok[b][n][c] = x[b][c][n] + pe(c,n)   (32x32 smem tile transpose)
__global__ void k_tok(const float* __restrict__ x) {
    __shared__ float tile[32][33];
    int b = blockIdx.z;
    int n0 = blockIdx.x << 5;
    int c0 = blockIdx.y << 5;
    int tx = threadIdx.x, ty = threadIdx.y;
    int c = c0 + ty, n = n0 + tx;
    tile[ty][tx] = x[((size_t)b * CDIM + c) * NTOK + n] + pe_val(c, n);
    __syncthreads();
    int nw = n0 + ty, cw = c0 + tx;
    g_tok[((size_t)b * NTOK + nw) * CDIM + cw] = tile[tx][ty];
}

// GEMM: out[m][c] = sum_k A[m][k] * W[c][k] + bias[c]
// MODE 0: A = g_tok, scatter into g_q/g_k/g_v per head:  ((b*8+h)*N + n)*32 + d
// MODE 1: A = g_att, write transposed to output: out[(b*C + c)*N + n]
template <int MODE>
__global__ void k_gemm(const float* __restrict__ W, const float* __restrict__ bias,
                       float* __restrict__ outp, int which) {
    const float* A = (MODE == 0) ? g_tok : g_att;
    float* dst;
    if (MODE == 0) dst = (which == 0) ? g_q : ((which == 1) ? g_k : g_v);
    else           dst = outp;

    __shared__ float Asm[64][33];
    __shared__ float Bsm[64][33];
    int m0 = blockIdx.x << 6;
    int c0 = blockIdx.y << 6;
    int tid = threadIdx.x;
    int tx = tid & 15, ty = tid >> 4;

    float acc[4][4];
#pragma unroll
    for (int i = 0; i < 4; i++)
#pragma unroll
        for (int j = 0; j < 4; j++) acc[i][j] = 0.f;

    for (int k0 = 0; k0 < CDIM; k0 += 32) {
#pragma unroll
        for (int u = 0; u < 8; u++) {
            int i = tid + u * 256;
            int r = i >> 5, kk = i & 31;
            Asm[r][kk] = A[(size_t)(m0 + r) * CDIM + k0 + kk];
            Bsm[r][kk] = W[(size_t)(c0 + r) * CDIM + k0 + kk];
        }
        __syncthreads();
#pragma unroll
        for (int kk = 0; kk < 32; kk++) {
            float a[4], bb[4];
#pragma unroll
            for (int i = 0; i < 4; i++) a[i] = Asm[ty * 4 + i][kk];
#pragma unroll
            for (int j = 0; j < 4; j++) bb[j] = Bsm[tx * 4 + j][kk];
#pragma unroll
            for (int i = 0; i < 4; i++)
#pragma unroll
                for (int j = 0; j < 4; j++) acc[i][j] += a[i] * bb[j];
        }
        __syncthreads();
    }

#pragma unroll
    for (int i = 0; i < 4; i++) {
        int m = m0 + ty * 4 + i;
        int bidx = m >> 12;   // m / NTOK
        int n = m & 4095;     // m % NTOK
#pragma unroll
        for (int j = 0; j < 4; j++) {
            int c = c0 + tx * 4 + j;
            float val = acc[i][j] + bias[c];
            if (MODE == 0) {
                int hd = c >> 5, d = c & 31;
                dst[(((size_t)(bidx * NHEAD + hd) * NTOK) + n) * DK + d] = val;
            } else {
                dst[((size_t)bidx * CDIM + c) * NTOK + n] = val;
            }
        }
    }
}

// Flash attention: one block = one (b,head) x 64-row query tile.
// 256 threads: 4 threads per query row (cg = col group), each owns 8 of 32 out dims.
// Per key tile of 64: S = Q K^T (interleaved j = cg + 4*jj), online softmax, O += P V.
__global__ void k_attn() {
    __shared__ float Ksm[64][36];  // pad 36: conflict-free float4 reads with j-stride-1 per cg
    __shared__ float Vsm[64][32];  // uniform-j reads -> no conflicts
    __shared__ float Psm[64][68];  // pad 68: conflict-free stores (4r+cg covers all banks)

    int bh = blockIdx.y;
    int m0 = blockIdx.x << 6;
    const float* Q = g_q + (size_t)bh * NTOK * DK;
    const float* K = g_k + (size_t)bh * NTOK * DK;
    const float* V = g_v + (size_t)bh * NTOK * DK;

    int tid = threadIdx.x;
    int r = tid >> 2;
    int cg = tid & 3;

    float4 qv[8];
    const float4* qrow = (const float4*)(Q + (size_t)(m0 + r) * DK);
#pragma unroll
    for (int i = 0; i < 8; i++) qv[i] = qrow[i];

    float m_i = -1e30f, l_i = 0.f;
    float4 o0 = {0.f, 0.f, 0.f, 0.f};
    float4 o1 = {0.f, 0.f, 0.f, 0.f};
    const float scale = 0.17677669529663687f;  // 1/sqrt(32)

    for (int t = 0; t < NTOK / 64; t++) {
        __syncthreads();  // previous tile's smem reads complete
        {
            const float4* Kg = (const float4*)(K + (size_t)t * 64 * DK);
            const float4* Vg = (const float4*)(V + (size_t)t * 64 * DK);
#pragma unroll
            for (int u = 0; u < 2; u++) {
                int i = tid + u * 256;      // float4 index 0..511
                int row = i >> 3, seg = i & 7;
                float4 kk4 = Kg[i];
                *(float4*)&Ksm[row][seg * 4] = kk4;
                float4 vv4 = Vg[i];
                *(float4*)&Vsm[row][seg * 4] = vv4;
            }
        }
        __syncthreads();

        // S row-slice: 16 interleaved columns j = cg + 4*jj
        float s[16];
#pragma unroll
        for (int jj = 0; jj < 16; jj++) s[jj] = 0.f;
#pragma unroll
        for (int d4 = 0; d4 < 8; d4++) {
            float4 q4 = qv[d4];
#pragma unroll
            for (int jj = 0; jj < 16; jj++) {
                int j = cg + (jj << 2);
                float4 k4 = *(const float4*)&Ksm[j][d4 * 4];
                s[jj] += q4.x * k4.x + q4.y * k4.y + q4.z * k4.z + q4.w * k4.w;
            }
        }

        float mt = -1e30f;
#pragma unroll
        for (int jj = 0; jj < 16; jj++) { s[jj] *= scale; mt = fmaxf(mt, s[jj]); }
        mt = fmaxf(mt, __shfl_xor_sync(0xffffffffu, mt, 1));
        mt = fmaxf(mt, __shfl_xor_sync(0xffffffffu, mt, 2));
        float m_new = fmaxf(m_i, mt);

        float lsum = 0.f;
#pragma unroll
        for (int jj = 0; jj < 16; jj++) {
            float p = __expf(s[jj] - m_new);
            Psm[r][cg + (jj << 2)] = p;
            lsum += p;
        }
        lsum += __shfl_xor_sync(0xffffffffu, lsum, 1);
        lsum += __shfl_xor_sync(0xffffffffu, lsum, 2);

        float alpha = __expf(m_i - m_new);
        l_i = l_i * alpha + lsum;
        m_i = m_new;
        o0.x *= alpha; o0.y *= alpha; o0.z *= alpha; o0.w *= alpha;
        o1.x *= alpha; o1.y *= alpha; o1.z *= alpha; o1.w *= alpha;

        __syncthreads();  // all Psm writes visible

#pragma unroll 8
        for (int j = 0; j < 64; j++) {
            float p = Psm[r][j];
            float4 v0 = *(const float4*)&Vsm[j][cg * 8];
            float4 v1 = *(const float4*)&Vsm[j][cg * 8 + 4];
            o0.x += p * v0.x; o0.y += p * v0.y; o0.z += p * v0.z; o0.w += p * v0.w;
            o1.x += p * v1.x; o1.y += p * v1.y; o1.z += p * v1.z; o1.w += p * v1.w;
        }
    }

    float inv = 1.f / l_i;
    o0.x *= inv; o0.y *= inv; o0.z *= inv; o0.w *= inv;
    o1.x *= inv; o1.y *= inv; o1.z *= inv; o1.w *= inv;

    int b = bh >> 3;
    int hd = bh & 7;
    int n = m0 + r;
    float* dst = g_att + ((size_t)(b * NTOK + n)) * CDIM + hd * DK + cg * 8;
    *(float4*)dst = o0;
    *(float4*)(dst + 4) = o1;
}

extern "C" void kernel_launch(void* const* d_in, const int* in_sizes, int n_in,
                              void* d_out, int out_size) {
    const float* x  = (const float*)d_in[0];
    const float* Wq = (const float*)d_in[1];
    const float* bq = (const float*)d_in[2];
    const float* Wk = (const float*)d_in[3];
    const float* bk = (const float*)d_in[4];
    const float* Wv = (const float*)d_in[5];
    const float* bv = (const float*)d_in[6];
    const float* Wo = (const float*)d_in[7];
    const float* bo = (const float*)d_in[8];
    float* out = (float*)d_out;

    dim3 g1(NTOK / 32, CDIM / 32, BATCH);
    k_tok<<<g1, dim3(32, 32)>>>(x);

    dim3 g2(BATCH * NTOK / 64, CDIM / 64);
    k_gemm<0><<<g2, 256>>>(Wq, bq, nullptr, 0);
    k_gemm<0><<<g2, 256>>>(Wk, bk, nullptr, 1);
    k_gemm<0><<<g2, 256>>>(Wv, bv, nullptr, 2);

    k_attn<<<dim3(NTOK / 64, BATCH * NHEAD), 256>>>();

    k_gemm<1><<<g2, 256>>>(Wo, bo, out, 0);
}

// round 4
// speedup vs baseline: 4.0743x; 4.0743x over previous
#include <cuda_runtime.h>
#include <math.h>
#include <stdint.h>

#define BATCH 2
#define CDIM 256
#define NTOK 4096
#define NHEAD 8
#define DK 32
#define DHALF 128

#define BR 128   // query rows per block (8 warps x 16 rows)
#define BC 64    // key/value rows per tile

// Scratch (allowed: __device__ globals)
__device__ float g_tok[BATCH * NTOK * CDIM];
__device__ float g_q[BATCH * NHEAD * NTOK * DK];
__device__ float g_k[BATCH * NHEAD * NTOK * DK];
__device__ float g_v[BATCH * NHEAD * NTOK * DK];
__device__ float g_att[BATCH * NTOK * CDIM];

// ---------------------------------------------------------------------------
// Positional encoding (faithful port)
// ---------------------------------------------------------------------------
__device__ __forceinline__ float pe_val(int c, int n) {
    int hh = n >> 6;
    int ww = n & 63;
    float pos;
    int cc;
    if (c < DHALF) { pos = (float)ww; cc = c; }
    else           { pos = (float)hh; cc = c - DHALF; }
    int j = cc >> 1;
    float dv = __expf(-(float)(2 * j) * 0.071955784156063940f);  // ln(1e4)/128
    float a = pos * dv;
    return (cc & 1) ? cosf(a) : sinf(a);
}

// tok[b][n][c] = x[b][c][n] + pe(c,n)
__global__ void k_tok(const float* __restrict__ x) {
    __shared__ float tile[32][33];
    int b = blockIdx.z;
    int n0 = blockIdx.x << 5;
    int c0 = blockIdx.y << 5;
    int tx = threadIdx.x, ty = threadIdx.y;
    int c = c0 + ty, n = n0 + tx;
    tile[ty][tx] = x[((size_t)b * CDIM + c) * NTOK + n] + pe_val(c, n);
    __syncthreads();
    int nw = n0 + ty, cw = c0 + tx;
    g_tok[((size_t)b * NTOK + nw) * CDIM + cw] = tile[tx][ty];
}

// ---------------------------------------------------------------------------
// fp32 GEMM (unchanged this round): out[m][c] = A[m][:] . W[c][:] + bias[c]
// ---------------------------------------------------------------------------
template <int MODE>
__global__ void k_gemm(const float* __restrict__ W, const float* __restrict__ bias,
                       float* __restrict__ outp, int which) {
    const float* A = (MODE == 0) ? g_tok : g_att;
    float* dst;
    if (MODE == 0) dst = (which == 0) ? g_q : ((which == 1) ? g_k : g_v);
    else           dst = outp;

    __shared__ float Asm[64][33];
    __shared__ float Bsm[64][33];
    int m0 = blockIdx.x << 6;
    int c0 = blockIdx.y << 6;
    int tid = threadIdx.x;
    int tx = tid & 15, ty = tid >> 4;

    float acc[4][4];
#pragma unroll
    for (int i = 0; i < 4; i++)
#pragma unroll
        for (int j = 0; j < 4; j++) acc[i][j] = 0.f;

    for (int k0 = 0; k0 < CDIM; k0 += 32) {
#pragma unroll
        for (int u = 0; u < 8; u++) {
            int i = tid + u * 256;
            int r = i >> 5, kk = i & 31;
            Asm[r][kk] = A[(size_t)(m0 + r) * CDIM + k0 + kk];
            Bsm[r][kk] = W[(size_t)(c0 + r) * CDIM + k0 + kk];
        }
        __syncthreads();
#pragma unroll
        for (int kk = 0; kk < 32; kk++) {
            float a[4], bb[4];
#pragma unroll
            for (int i = 0; i < 4; i++) a[i] = Asm[ty * 4 + i][kk];
#pragma unroll
            for (int j = 0; j < 4; j++) bb[j] = Bsm[tx * 4 + j][kk];
#pragma unroll
            for (int i = 0; i < 4; i++)
#pragma unroll
                for (int j = 0; j < 4; j++) acc[i][j] += a[i] * bb[j];
        }
        __syncthreads();
    }

#pragma unroll
    for (int i = 0; i < 4; i++) {
        int m = m0 + ty * 4 + i;
        int bidx = m >> 12;
        int n = m & 4095;
#pragma unroll
        for (int j = 0; j < 4; j++) {
            int c = c0 + tx * 4 + j;
            float val = acc[i][j] + bias[c];
            if (MODE == 0) {
                int hd = c >> 5, d = c & 31;
                dst[(((size_t)(bidx * NHEAD + hd) * NTOK) + n) * DK + d] = val;
            } else {
                dst[((size_t)bidx * CDIM + c) * NTOK + n] = val;
            }
        }
    }
}

// ---------------------------------------------------------------------------
// tf32 tensor-core flash attention
// ---------------------------------------------------------------------------
__device__ __forceinline__ uint32_t f2tf32(float f) {
    uint32_t r;
    asm("cvt.rna.tf32.f32 %0, %1;" : "=r"(r) : "f"(f));
    return r;
}

__device__ __forceinline__ void mma_tf32(float* d, const uint32_t* a, const uint32_t* b) {
    asm volatile(
        "mma.sync.aligned.m16n8k8.row.col.f32.tf32.tf32.f32 "
        "{%0,%1,%2,%3}, {%4,%5,%6,%7}, {%8,%9}, {%0,%1,%2,%3};"
        : "+f"(d[0]), "+f"(d[1]), "+f"(d[2]), "+f"(d[3])
        : "r"(a[0]), "r"(a[1]), "r"(a[2]), "r"(a[3]), "r"(b[0]), "r"(b[1]));
}

// One block = one (b,head) x 128-query-row tile. 8 warps, 16 rows each.
// Key loop over 64-row K/V tiles; tf32 mma for QK^T and P.V; online softmax.
__global__ __launch_bounds__(256) void k_attn_tc() {
    // Strides chosen so every mma fragment gather hits 32 distinct banks:
    // Ksm stride 36: bank=(4*g+tg);  Vsm stride 40: bank=(8*tg+g);
    // Psm stride 76: bank=(12*g+tg) -- all bijective over the 32 lanes.
    __shared__ uint32_t Ksm[BC][36];
    __shared__ uint32_t Vsm[BC][40];
    __shared__ uint32_t Psm[BR][76];

    int bh = blockIdx.y;
    int m0 = blockIdx.x * BR;
    const float* Q = g_q + (size_t)bh * NTOK * DK;
    const float* K = g_k + (size_t)bh * NTOK * DK;
    const float* V = g_v + (size_t)bh * NTOK * DK;

    int tid = threadIdx.x;
    int warp = tid >> 5, lane = tid & 31;
    int g = lane >> 2;        // groupID (row within fragment)
    int tg = lane & 3;        // threadID_in_group

    const float scale = 0.17677669529663687f;  // 1/sqrt(32), folded into Q

    // --- Q fragments (A of m16n8k8), loaded once, pre-scaled, tf32 ---
    // kt-th 8-col slice of Q[16w..16w+15][0..31]
    uint32_t qa[4][4];
    {
        int r0 = m0 + warp * 16;
#pragma unroll
        for (int kt = 0; kt < 4; kt++) {
            int c = 8 * kt + tg;
            qa[kt][0] = f2tf32(Q[(size_t)(r0 + g) * DK + c] * scale);
            qa[kt][1] = f2tf32(Q[(size_t)(r0 + g + 8) * DK + c] * scale);
            qa[kt][2] = f2tf32(Q[(size_t)(r0 + g) * DK + c + 4] * scale);
            qa[kt][3] = f2tf32(Q[(size_t)(r0 + g + 8) * DK + c + 4] * scale);
        }
    }

    // Online softmax state for this thread's two rows (g, g+8)
    float m_i0 = -1e30f, m_i1 = -1e30f;
    float l_i0 = 0.f, l_i1 = 0.f;
    float o[4][4];   // O(16x32): 4 n-tiles of 8 cols, C-fragment layout
#pragma unroll
    for (int dt = 0; dt < 4; dt++)
#pragma unroll
        for (int i = 0; i < 4; i++) o[dt][i] = 0.f;

    for (int t = 0; t < NTOK / BC; t++) {
        __syncthreads();  // prior tile's Vsm reads complete before refill

        // --- fill K and V tiles (tf32-converted at store time) ---
        {
            const float4* Kg = (const float4*)(K + (size_t)t * BC * DK);
            const float4* Vg = (const float4*)(V + (size_t)t * BC * DK);
#pragma unroll
            for (int u = 0; u < 2; u++) {
                int i = tid + u * 256;        // 512 float4 = 64x32 floats
                int row = i >> 3, seg = (i & 7) * 4;
                float4 kk4 = Kg[i];
                Ksm[row][seg + 0] = f2tf32(kk4.x);
                Ksm[row][seg + 1] = f2tf32(kk4.y);
                Ksm[row][seg + 2] = f2tf32(kk4.z);
                Ksm[row][seg + 3] = f2tf32(kk4.w);
                float4 vv4 = Vg[i];
                Vsm[row][seg + 0] = f2tf32(vv4.x);
                Vsm[row][seg + 1] = f2tf32(vv4.y);
                Vsm[row][seg + 2] = f2tf32(vv4.z);
                Vsm[row][seg + 3] = f2tf32(vv4.w);
            }
        }
        __syncthreads();

        // --- S = (Q*scale) K^T : 8 n-tiles x 4 k-tiles of m16n8k8 ---
        float c[8][4];
#pragma unroll
        for (int nt = 0; nt < 8; nt++) {
#pragma unroll
            for (int i = 0; i < 4; i++) c[nt][i] = 0.f;
#pragma unroll
            for (int kt = 0; kt < 4; kt++) {
                uint32_t b[2];
                // B[k][n] = K[8nt+n][8kt+k]; b0=(k=tg,n=g), b1=(k=tg+4,n=g)
                b[0] = Ksm[8 * nt + g][8 * kt + tg];
                b[1] = Ksm[8 * nt + g][8 * kt + tg + 4];
                mma_tf32(c[nt], qa[kt], b);
            }
        }

        // --- online softmax over the 64 columns of this tile ---
        float mx0 = -1e30f, mx1 = -1e30f;
#pragma unroll
        for (int nt = 0; nt < 8; nt++) {
            mx0 = fmaxf(mx0, fmaxf(c[nt][0], c[nt][1]));
            mx1 = fmaxf(mx1, fmaxf(c[nt][2], c[nt][3]));
        }
        mx0 = fmaxf(mx0, __shfl_xor_sync(0xffffffffu, mx0, 1));
        mx0 = fmaxf(mx0, __shfl_xor_sync(0xffffffffu, mx0, 2));
        mx1 = fmaxf(mx1, __shfl_xor_sync(0xffffffffu, mx1, 1));
        mx1 = fmaxf(mx1, __shfl_xor_sync(0xffffffffu, mx1, 2));

        float mn0 = fmaxf(m_i0, mx0);
        float mn1 = fmaxf(m_i1, mx1);
        float alpha0 = __expf(m_i0 - mn0);
        float alpha1 = __expf(m_i1 - mn1);

        int row0 = warp * 16 + g;
        int row1 = row0 + 8;
        float ls0 = 0.f, ls1 = 0.f;
#pragma unroll
        for (int nt = 0; nt < 8; nt++) {
            float p0 = __expf(c[nt][0] - mn0);
            float p1 = __expf(c[nt][1] - mn0);
            float p2 = __expf(c[nt][2] - mn1);
            float p3 = __expf(c[nt][3] - mn1);
            ls0 += p0 + p1;
            ls1 += p2 + p3;
            int col = 8 * nt + 2 * tg;
            Psm[row0][col]     = f2tf32(p0);
            Psm[row0][col + 1] = f2tf32(p1);
            Psm[row1][col]     = f2tf32(p2);
            Psm[row1][col + 1] = f2tf32(p3);
        }
        ls0 += __shfl_xor_sync(0xffffffffu, ls0, 1);
        ls0 += __shfl_xor_sync(0xffffffffu, ls0, 2);
        ls1 += __shfl_xor_sync(0xffffffffu, ls1, 1);
        ls1 += __shfl_xor_sync(0xffffffffu, ls1, 2);

        l_i0 = l_i0 * alpha0 + ls0;
        l_i1 = l_i1 * alpha1 + ls1;
        m_i0 = mn0;
        m_i1 = mn1;

#pragma unroll
        for (int dt = 0; dt < 4; dt++) {
            o[dt][0] *= alpha0; o[dt][1] *= alpha0;
            o[dt][2] *= alpha1; o[dt][3] *= alpha1;
        }

        __syncwarp();  // Psm rows are warp-private: warp-level sync suffices

        // --- O += P V : k over 64 (8 k-tiles), n over 32 (4 d-tiles) ---
#pragma unroll
        for (int kt = 0; kt < 8; kt++) {
            uint32_t a[4];
            int r0 = warp * 16;
            a[0] = Psm[r0 + g][8 * kt + tg];
            a[1] = Psm[r0 + g + 8][8 * kt + tg];
            a[2] = Psm[r0 + g][8 * kt + tg + 4];
            a[3] = Psm[r0 + g + 8][8 * kt + tg + 4];
#pragma unroll
            for (int dt = 0; dt < 4; dt++) {
                uint32_t b[2];
                // B[k][n] = V[8kt+k][8dt+n]
                b[0] = Vsm[8 * kt + tg][8 * dt + g];
                b[1] = Vsm[8 * kt + tg + 4][8 * dt + g];
                mma_tf32(o[dt], a, b);
            }
        }
        __syncwarp();  // PV reads of Psm done before next tile overwrites
    }

    // --- normalize and write out to g_att[b][n][head*32 + d] ---
    float inv0 = 1.f / l_i0;
    float inv1 = 1.f / l_i1;
    int b_ = bh >> 3;
    int hd = bh & 7;
    int n0 = m0 + warp * 16 + g;
#pragma unroll
    for (int dt = 0; dt < 4; dt++) {
        int col = hd * DK + 8 * dt + 2 * tg;
        float2 w0 = make_float2(o[dt][0] * inv0, o[dt][1] * inv0);
        float2 w1 = make_float2(o[dt][2] * inv1, o[dt][3] * inv1);
        *(float2*)&g_att[((size_t)(b_ * NTOK + n0)) * CDIM + col] = w0;
        *(float2*)&g_att[((size_t)(b_ * NTOK + n0 + 8)) * CDIM + col] = w1;
    }
}

extern "C" void kernel_launch(void* const* d_in, const int* in_sizes, int n_in,
                              void* d_out, int out_size) {
    const float* x  = (const float*)d_in[0];
    const float* Wq = (const float*)d_in[1];
    const float* bq = (const float*)d_in[2];
    const float* Wk = (const float*)d_in[3];
    const float* bk = (const float*)d_in[4];
    const float* Wv = (const float*)d_in[5];
    const float* bv = (const float*)d_in[6];
    const float* Wo = (const float*)d_in[7];
    const float* bo = (const float*)d_in[8];
    float* out = (float*)d_out;

    dim3 g1(NTOK / 32, CDIM / 32, BATCH);
    k_tok<<<g1, dim3(32, 32)>>>(x);

    dim3 g2(BATCH * NTOK / 64, CDIM / 64);
    k_gemm<0><<<g2, 256>>>(Wq, bq, nullptr, 0);
    k_gemm<0><<<g2, 256>>>(Wk, bk, nullptr, 1);
    k_gemm<0><<<g2, 256>>>(Wv, bv, nullptr, 2);

    k_attn_tc<<<dim3(NTOK / BR, BATCH * NHEAD), 256>>>();

    k_gemm<1><<<g2, 256>>>(Wo, bo, out, 0);
}